// round 16
// baseline (speedup 1.0000x reference)
#include <cuda_runtime.h>
#include <cuda_bf16.h>
#include <math.h>
#include <stdint.h>

// Problem constants
#define BB 8
#define LL 2048
#define DD 512
#define KK 4096
#define NROWS (BB * LL)          // 16384
#define QELEMS (NROWS * DD)      // 8388608
#define DECAYF 0.99f
#define EPSF 1e-5f
#define KL 1024                  // limb layout: [h(512) | m(512)]
#define NSPLIT 2                 // code-range split across blockIdx.y
#define SMEM_STAGE 65536         // 2 pipeline stages x (A 16KB + B 16KB)
#define MARGIN 1e-2f             // refine window (>> 4e-3 worst-case approx err)
#define CAND_CAP 64

// ---------------- scratch (device globals: no allocation allowed) ----------------
__device__ float g_c2[KK];
__device__ float g_x2[NROWS];
__device__ float g_counts[KK];
__device__ float g_dw[KK * DD];
__device__ float g_avgc[KK];
__device__ float g_cbnew[KK * DD];
__device__ float g_scal[4];                         // [0]=N, [1]=loss sum, [2]=bias
__device__ int   g_idx[NROWS];
__device__ float g_d2[(size_t)NROWS * KK];          // approx d2 (268 MB)
__device__ __nv_bfloat16 g_xe[(size_t)NROWS * KL];  // x limbs (33 MB)
__device__ __nv_bfloat16 g_ce[(size_t)KK * KL];     // codebook limbs (8.4 MB)

// ---------------- PTX helpers (portable sm_80+ ops only) ----------------
__device__ __forceinline__ uint32_t smem_u32(const void* p) {
    uint32_t a;
    asm("{ .reg .u64 t; cvta.to.shared.u64 t, %1; cvt.u32.u64 %0, t; }"
        : "=r"(a) : "l"(p));
    return a;
}
__device__ __forceinline__ void cp_async16(uint32_t dst, const void* src) {
    asm volatile("cp.async.cg.shared.global [%0], [%1], 16;"
                 :: "r"(dst), "l"(src) : "memory");
}
__device__ __forceinline__ void cp_commit() {
    asm volatile("cp.async.commit_group;" ::: "memory");
}
template <int N> __device__ __forceinline__ void cp_wait() {
    asm volatile("cp.async.wait_group %0;" :: "n"(N) : "memory");
}
__device__ __forceinline__ void ldsm_x4(uint32_t& r0, uint32_t& r1, uint32_t& r2,
                                        uint32_t& r3, uint32_t addr) {
    asm volatile("ldmatrix.sync.aligned.m8n8.x4.shared.b16 {%0,%1,%2,%3}, [%4];"
                 : "=r"(r0), "=r"(r1), "=r"(r2), "=r"(r3) : "r"(addr));
}
__device__ __forceinline__ void mma_bf16(float* c, const uint32_t* a,
                                         uint32_t b0, uint32_t b1) {
    asm volatile(
        "mma.sync.aligned.m16n8k16.row.col.f32.bf16.bf16.f32 "
        "{%0,%1,%2,%3}, {%4,%5,%6,%7}, {%8,%9}, {%0,%1,%2,%3};"
        : "+f"(c[0]), "+f"(c[1]), "+f"(c[2]), "+f"(c[3])
        : "r"(a[0]), "r"(a[1]), "r"(a[2]), "r"(a[3]), "r"(b0), "r"(b1));
}

// ---------------- K0: zero scratch ----------------
__global__ void zero_kernel() {
    const int total = KK * DD + KK + 2;
    for (int i = blockIdx.x * blockDim.x + threadIdx.x; i < total;
         i += gridDim.x * blockDim.x) {
        if (i < KK * DD)            g_dw[i] = 0.0f;
        else if (i < KK * DD + KK)  g_counts[i - KK * DD] = 0.0f;
        else                        g_scal[i - KK * DD - KK] = 0.0f;
    }
}

// ---------------- K1: bf16 2-limb Dekker decomposition ----------------
__global__ void decomp_kernel(const float* __restrict__ x, const float* __restrict__ cb) {
    const int total = (NROWS + KK) * DD;
    for (int i = blockIdx.x * blockDim.x + threadIdx.x; i < total;
         i += gridDim.x * blockDim.x) {
        bool isx = i < NROWS * DD;
        int  j   = isx ? i : i - NROWS * DD;
        float v  = isx ? x[j] : cb[j];
        __nv_bfloat16 h = __float2bfloat16(v);
        float r1 = v - __bfloat162float(h);           // exact (Sterbenz)
        __nv_bfloat16 m = __float2bfloat16(r1);
        int row = j >> 9, col = j & 511;
        size_t base = (size_t)row * KL + col;
        if (isx) { g_xe[base] = h; g_xe[base + 512] = m; }
        else     { g_ce[base] = h; g_ce[base + 512] = m; }
    }
}

// ---------------- K2: sums of squares (fp32 originals) ----------------
__global__ void sumsq_kernel(const float* __restrict__ cb, const float* __restrict__ x) {
    int row  = (blockIdx.x * blockDim.x + threadIdx.x) >> 5;
    int lane = threadIdx.x & 31;
    if (row >= KK + NROWS) return;
    const float* p = (row < KK) ? (cb + (size_t)row * DD)
                                : (x + (size_t)(row - KK) * DD);
    float s = 0.0f;
    #pragma unroll
    for (int d = lane; d < DD; d += 32) { float v = p[d]; s += v * v; }
    #pragma unroll
    for (int o = 16; o > 0; o >>= 1) s += __shfl_xor_sync(0xFFFFFFFFu, s, o);
    if (lane == 0) {
        if (row < KK) g_c2[row] = s;
        else          g_x2[row - KK] = s;
    }
}

// ---------------- K3: HMMA 2-limb GEMM, 2-stage cp.async pipeline ----------------
// grid (128 m-tiles, 2 n-splits), 256 threads = 8 warps (2m x 4n), warp m64n32.
// Stage = k32; stage tile row (128B) = [32 h bf16 | 32 m bf16], XOR-swizzled.
// 2 stages x (A 16KB + B 16KB) = 64KB -> 2 CTAs/SM; loads overlap compute.
__global__ __launch_bounds__(256, 2) void argmin_kernel() {
    extern __shared__ __align__(128) char dynsm[];
    const uint32_t sm0 = smem_u32(dynsm);

    const int tid  = threadIdx.x;
    const int wid  = tid >> 5, lane = tid & 31;
    const int wm   = wid >> 2, wn = wid & 3;        // warp grid 2 x 4
    const int m0   = blockIdx.x * 128;
    const int nblk = blockIdx.y * (KK / NSPLIT);    // 2048-wide n range

    const int lrow = lane & 15, lhalf = lane >> 4;
    const int lr7  = lrow & 7;

    // cp.async per-thread geometry: 8 units of 16B per stage
    // unit u = s*256 + tid, s in 0..7; mat = u>>10 (0=A,1=B); row=(u&1023)>>3; q=u&7
    // q<4 -> h limb cols, q>=4 -> m limb cols (+512 in K dim)

    for (int nt = 0; nt < KK / NSPLIT / 128; nt++) {
        const int n0 = nblk + nt * 128;

        float acc[4][4][4];
        #pragma unroll
        for (int i = 0; i < 4; i++)
            #pragma unroll
            for (int j = 0; j < 4; j++)
                #pragma unroll
                for (int c = 0; c < 4; c++) acc[i][j][c] = 0.0f;

        // ---- stage loader (kb = k32 index, buf = 0/1) ----
        auto load_stage = [&](int kb, int buf) {
            const uint32_t sbase = sm0 + buf * 32768;
            #pragma unroll
            for (int s = 0; s < 8; s++) {
                int u   = s * 256 + tid;             // 0..2047
                int mat = u >> 10;                   // 0 = A, 1 = B
                int rem = u & 1023;
                int row = rem >> 3, q = rem & 7;
                uint32_t dst = sbase + mat * 16384
                             + row * 128 + ((q ^ (row & 7)) << 4);
                int kcol = (q < 4) ? (kb * 32 + q * 8)
                                   : (512 + kb * 32 + (q - 4) * 8);
                const __nv_bfloat16* src = (mat == 0)
                    ? g_xe + (size_t)(m0 + row) * KL + kcol
                    : g_ce + (size_t)(n0 + row) * KL + kcol;
                cp_async16(dst, src);
            }
        };

        // ---- prime stage 0 ----
        load_stage(0, 0);
        cp_commit();

        #pragma unroll 1
        for (int kb = 0; kb < 16; kb++) {
            const int cur = kb & 1;
            if (kb < 15) { load_stage(kb + 1, cur ^ 1); cp_commit(); cp_wait<1>(); }
            else         { cp_wait<0>(); }
            __syncthreads();

            const uint32_t sA = sm0 + cur * 32768;
            const uint32_t sB = sA + 16384;

            #pragma unroll
            for (int g = 0; g < 2; g++) {           // two k16 groups per k32
                const int uH = ((g * 2 + lhalf) ^ lr7) << 4;          // h units
                const int uM = (((4 + g * 2 + lhalf)) ^ lr7) << 4;    // m units
                uint32_t ah[4][4], am[4][4];
                #pragma unroll
                for (int im = 0; im < 4; im++) {
                    uint32_t rb = sA + (wm * 64 + im * 16 + lrow) * 128;
                    ldsm_x4(ah[im][0], ah[im][1], ah[im][2], ah[im][3], rb + uH);
                    ldsm_x4(am[im][0], am[im][1], am[im][2], am[im][3], rb + uM);
                }
                uint32_t bh[2][4], bm[2][4];
                #pragma unroll
                for (int nh = 0; nh < 2; nh++) {
                    uint32_t rb = sB + (wn * 32 + nh * 16 + lrow) * 128;
                    ldsm_x4(bh[nh][0], bh[nh][1], bh[nh][2], bh[nh][3], rb + uH);
                    ldsm_x4(bm[nh][0], bm[nh][1], bm[nh][2], bm[nh][3], rb + uM);
                }
                #pragma unroll
                for (int im = 0; im < 4; im++) {
                    // hh
                    mma_bf16(acc[im][0], ah[im], bh[0][0], bh[0][2]);
                    mma_bf16(acc[im][1], ah[im], bh[0][1], bh[0][3]);
                    mma_bf16(acc[im][2], ah[im], bh[1][0], bh[1][2]);
                    mma_bf16(acc[im][3], ah[im], bh[1][1], bh[1][3]);
                    // hm
                    mma_bf16(acc[im][0], ah[im], bm[0][0], bm[0][2]);
                    mma_bf16(acc[im][1], ah[im], bm[0][1], bm[0][3]);
                    mma_bf16(acc[im][2], ah[im], bm[1][0], bm[1][2]);
                    mma_bf16(acc[im][3], ah[im], bm[1][1], bm[1][3]);
                    // mh
                    mma_bf16(acc[im][0], am[im], bh[0][0], bh[0][2]);
                    mma_bf16(acc[im][1], am[im], bh[0][1], bh[0][3]);
                    mma_bf16(acc[im][2], am[im], bh[1][0], bh[1][2]);
                    mma_bf16(acc[im][3], am[im], bh[1][1], bh[1][3]);
                }
            }
            __syncthreads();    // compute done before next prefetch overwrites
        }

        // epilogue: store approx d2 = (x2 - 2*xc) + c2 for every (row, col)
        const int colb = n0 + wn * 32 + ((lane & 3) << 1);
        #pragma unroll
        for (int im = 0; im < 4; im++) {
            #pragma unroll
            for (int h = 0; h < 2; h++) {
                int row = m0 + wm * 64 + im * 16 + (lane >> 2) + h * 8;
                float x2v = g_x2[row];
                float* drow = g_d2 + (size_t)row * KK;
                #pragma unroll
                for (int j = 0; j < 4; j++) {
                    int c0 = colb + j * 8;
                    float2 dv;
                    dv.x = (x2v - 2.0f * acc[im][j][h * 2 + 0]) + g_c2[c0];
                    dv.y = (x2v - 2.0f * acc[im][j][h * 2 + 1]) + g_c2[c0 + 1];
                    *(float2*)(drow + c0) = dv;
                }
            }
        }
    }
}

// ---------------- K3b: exact fp32 refine within margin of approx min ----------------
__global__ void refine_kernel(const float* __restrict__ x, const float* __restrict__ cb) {
    __shared__ int scnt[8];
    __shared__ int scol[8][CAND_CAP];
    const int warp = threadIdx.x >> 5, lane = threadIdx.x & 31;
    const int r = blockIdx.x * 8 + warp;

    const float4* drow = (const float4*)(g_d2 + (size_t)r * KK);
    float mn = 3.4e38f;
    #pragma unroll 4
    for (int i = 0; i < 32; i++) {
        float4 v = drow[lane + i * 32];
        mn = fminf(mn, fminf(fminf(v.x, v.y), fminf(v.z, v.w)));
    }
    #pragma unroll
    for (int o = 16; o > 0; o >>= 1) mn = fminf(mn, __shfl_xor_sync(0xFFFFFFFFu, mn, o));
    const float thr = mn + MARGIN;

    if (lane == 0) scnt[warp] = 0;
    __syncwarp();
    #pragma unroll 4
    for (int i = 0; i < 32; i++) {
        float4 v = drow[lane + i * 32];
        int base = (lane + i * 32) * 4;
        #pragma unroll
        for (int c = 0; c < 4; c++) {
            float dv = (c == 0) ? v.x : (c == 1) ? v.y : (c == 2) ? v.z : v.w;
            if (dv <= thr) {
                int p = atomicAdd(&scnt[warp], 1);
                if (p < CAND_CAP) scol[warp][p] = base + c;
            }
        }
    }
    __syncwarp();
    int cnt = min(scnt[warp], CAND_CAP);

    const float* xr = x + (size_t)r * DD;
    float xl[16];
    #pragma unroll
    for (int t = 0; t < 16; t++) xl[t] = xr[lane * 16 + t];
    float x2v = g_x2[r];

    unsigned long long bkey = 0xFFFFFFFFFFFFFFFFull;
    for (int ci = 0; ci < cnt; ci++) {
        int col = scol[warp][ci];
        const float* cr = cb + (size_t)col * DD;
        float s = 0.0f;
        #pragma unroll
        for (int t = 0; t < 16; t++) s += xl[t] * cr[lane * 16 + t];
        #pragma unroll
        for (int o = 16; o > 0; o >>= 1) s += __shfl_xor_sync(0xFFFFFFFFu, s, o);
        float d2 = (x2v - 2.0f * s) + g_c2[col];
        unsigned long long k =
            ((unsigned long long)__float_as_uint(d2) << 32) | (unsigned)col;
        if (k < bkey) bkey = k;
    }
    if (lane == 0) g_idx[r] = (int)(bkey & 0xFFFFFFFFull);
}

// ---------------- K4: scatter-add counts and dw ----------------
__global__ void scatter_kernel(const float* __restrict__ x) {
    int w    = (blockIdx.x * blockDim.x + threadIdx.x) >> 5;
    int lane = threadIdx.x & 31;
    if (w >= NROWS) return;
    int idx = g_idx[w];
    if (lane == 0) atomicAdd(&g_counts[idx], 1.0f);
    const float* xr = x + (size_t)w * DD;
    float* dwr = g_dw + (size_t)idx * DD;
    #pragma unroll
    for (int d = lane; d < DD; d += 32) atomicAdd(&dwr[d], xr[d]);
}

// ---------------- K5: EMA cluster stats, bias, N ----------------
__global__ void stats_kernel(const float* __restrict__ hidden_cluster,
                             const float* __restrict__ count) {
    __shared__ float sred[1024];
    int t = threadIdx.x;
    float cnt1 = count[0] + 1.0f;
    float bias = 1.0f - exp2f(cnt1 * log2f(DECAYF));
    float local = 0.0f;
    for (int k = t; k < KK; k += 1024) {
        float hc = hidden_cluster[k] * DECAYF + (1.0f - DECAYF) * g_counts[k];
        float a  = hc / bias;
        g_avgc[k] = a;
        local += a;
    }
    sred[t] = local;
    __syncthreads();
    for (int s = 512; s > 0; s >>= 1) {
        if (t < s) sred[t] += sred[t + s];
        __syncthreads();
    }
    if (t == 0) { g_scal[0] = sred[0]; g_scal[2] = bias; }
}

// ---------------- K6: codebook_new ----------------
__global__ void cbnew_kernel(const float* __restrict__ hidden_dw) {
    int i = blockIdx.x * blockDim.x + threadIdx.x;
    if (i >= KK * DD) return;
    float N    = g_scal[0];
    float bias = g_scal[2];
    int   k    = i >> 9;
    float avgdw = (hidden_dw[i] * DECAYF + (1.0f - DECAYF) * g_dw[i]) / bias;
    float cc    = (g_avgc[k] + EPSF) / (N + 4096.0f * EPSF) * N;
    g_cbnew[i]  = avgdw / cc;
}

// ---------------- K7: gather quantized + loss partials + indices ----------------
__global__ void output_kernel(const float* __restrict__ x, float* __restrict__ out,
                              int out_size) {
    __shared__ float sred[128];
    int r = blockIdx.x;
    int t = threadIdx.x;
    int idx = g_idx[r];
    const float4* q4 = (const float4*)(g_cbnew + (size_t)idx * DD);
    const float4* x4 = (const float4*)(x + (size_t)r * DD);
    float4*       o4 = (float4*)(out + (size_t)r * DD);
    float4 q  = q4[t];
    float4 xv = x4[t];
    float4 o;
    o.x = xv.x + (q.x - xv.x);
    o.y = xv.y + (q.y - xv.y);
    o.z = xv.z + (q.z - xv.z);
    o.w = xv.w + (q.w - xv.w);
    float dx = xv.x - o.x, dy = xv.y - o.y, dz = xv.z - o.z, dw = xv.w - o.w;
    float local = dx * dx + dy * dy + dz * dz + dw * dw;
    o4[t] = o;
    sred[t] = local;
    __syncthreads();
    for (int s = 64; s > 0; s >>= 1) {
        if (t < s) sred[t] += sred[t + s];
        __syncthreads();
    }
    if (t == 0) {
        atomicAdd(&g_scal[1], sred[0]);
        if (out_size >= QELEMS + 1 + NROWS)
            out[QELEMS + 1 + r] = (float)idx;
    }
}

// ---------------- K8: finalize loss ----------------
__global__ void finalize_kernel(float* __restrict__ out, int out_size) {
    if (out_size > QELEMS)
        out[QELEMS] = 0.5f * (g_scal[1] / (float)QELEMS);
}

// ---------------- launch ----------------
extern "C" void kernel_launch(void* const* d_in, const int* in_sizes, int n_in,
                              void* d_out, int out_size) {
    const float* x              = (const float*)d_in[0];
    const float* codebook       = (const float*)d_in[1];
    const float* hidden_cluster = (const float*)d_in[2];
    const float* hidden_dw      = (const float*)d_in[3];
    const float* count          = (const float*)d_in[4];
    float* out = (float*)d_out;

    cudaFuncSetAttribute(argmin_kernel,
                         cudaFuncAttributeMaxDynamicSharedMemorySize, SMEM_STAGE);

    zero_kernel<<<2048, 1024>>>();
    decomp_kernel<<<4096, 512>>>(x, codebook);
    sumsq_kernel<<<(KK + NROWS) / 8, 256>>>(codebook, x);
    argmin_kernel<<<dim3(NROWS / 128, NSPLIT), 256, SMEM_STAGE>>>();
    refine_kernel<<<NROWS / 8, 256>>>(x, codebook);
    scatter_kernel<<<NROWS / 8, 256>>>(x);
    stats_kernel<<<1, 1024>>>(hidden_cluster, count);
    cbnew_kernel<<<(KK * DD) / 512, 512>>>(hidden_dw);
    output_kernel<<<NROWS, 128>>>(x, out, out_size);
    finalize_kernel<<<1, 1>>>(out, out_size);
}